// round 6
// baseline (speedup 1.0000x reference)
#include <cuda_runtime.h>

// YOLO-v1 style loss: S=7, B=2, C=20
// prediction: [N,7,7,30] f32, target: [N,7,7,25] f32 -> scalar f32
//
// HBM-bound streaming reduction. float4 (LDG.128) staging into contiguous
// SMEM for coalescing + high MLP; per-cell compute reads from SMEM.
// Single-kernel deterministic reduction via threadfence + ticket counter
// (last block sums partials in fixed order with L1-bypassing __ldcg loads;
// no float atomics).

#define S7 7
#define CELLS_PER_IMG 49
#define PRED_CH 30
#define TGT_CH 25
#define BLOCK 128

#define PRED_F4 ((BLOCK * PRED_CH) / 4)   // 960
#define TGT_F4  ((BLOCK * TGT_CH) / 4)    // 800

__device__ float g_partials[65536];
__device__ unsigned int g_ticket = 0;

__device__ __forceinline__ float warp_reduce(float v) {
#pragma unroll
    for (int o = 16; o > 0; o >>= 1) v += __shfl_down_sync(0xFFFFFFFFu, v, o);
    return v;
}

__global__ void __launch_bounds__(BLOCK) yolo_loss_kernel(
    const float* __restrict__ pred,
    const float* __restrict__ targ,
    float* __restrict__ out,
    int cells, int nblocks)
{
    __shared__ float sp[BLOCK * PRED_CH];   // 15360 B, contiguous
    __shared__ float st[BLOCK * TGT_CH];    // 12800 B, contiguous
    __shared__ float swarp[BLOCK / 32];
    __shared__ bool s_last;

    const int tid = threadIdx.x;
    const int base = blockIdx.x * BLOCK;           // first cell of this block
    const int count = min(BLOCK, cells - base);

    if (count == BLOCK) {
        // ---- float4 staging; single flat loop over both tensors so ptxas
        //      front-batches all LDG.128s (max MLP) ----
        const float4* gp4 = (const float4*)(pred + (size_t)base * PRED_CH);
        const float4* gt4 = (const float4*)(targ + (size_t)base * TGT_CH);
        float4* sp4 = (float4*)sp;
        float4* st4 = (float4*)st;
#pragma unroll
        for (int r = 0; r < (PRED_F4 + TGT_F4 + BLOCK - 1) / BLOCK; r++) {  // 14 rounds
            const int j = r * BLOCK + tid;
            if (j < PRED_F4) {
                sp4[j] = __ldcs(gp4 + j);
            } else if (j < PRED_F4 + TGT_F4) {
                const int k = j - PRED_F4;
                st4[k] = __ldcs(gt4 + k);
            }
        }
    } else {
        // tail block: scalar staging
        const float* gp = pred + (size_t)base * PRED_CH;
        for (int j = tid; j < count * PRED_CH; j += BLOCK) sp[j] = gp[j];
        const float* gt = targ + (size_t)base * TGT_CH;
        for (int j = tid; j < count * TGT_CH; j += BLOCK) st[j] = gt[j];
    }
    __syncthreads();

    float loss = 0.0f;
    if (tid < count) {
        const float* p = sp + tid * PRED_CH;
        const float* t = st + tid * TGT_CH;

        const int gi   = base + tid;
        const int cell = gi % CELLS_PER_IMG;
        const float frow = (float)(cell / S7);
        const float fcol = (float)(cell % S7);

        // ---- ground-truth corner box ----
        const float gw = t[2], gh = t[3];
        const float gcx = (t[0] + fcol) / 7.0f;
        const float gcy = (t[1] + frow) / 7.0f;
        const float gx1 = gcx - gw * 0.5f, gy1 = gcy - gh * 0.5f;
        const float gx2 = gcx + gw * 0.5f, gy2 = gcy + gh * 0.5f;
        const float garea = fabsf((gx2 - gx1) * (gy2 - gy1));

        // ---- IOU for the two predicted boxes ----
        float iou0 = 0.0f, iou1 = 0.0f;
#pragma unroll
        for (int b = 0; b < 2; b++) {
            const float* q = p + 5 * b;
            const float w = q[2], h = q[3];
            const float cx = (q[0] + fcol) / 7.0f;
            const float cy = (q[1] + frow) / 7.0f;
            const float x1 = cx - w * 0.5f, y1 = cy - h * 0.5f;
            const float x2 = cx + w * 0.5f, y2 = cy + h * 0.5f;
            const float ix1 = fmaxf(x1, gx1), iy1 = fmaxf(y1, gy1);
            const float ix2 = fminf(x2, gx2), iy2 = fminf(y2, gy2);
            const float inter = fmaxf(ix2 - ix1, 0.0f) * fmaxf(iy2 - iy1, 0.0f);
            const float a1 = fabsf((x2 - x1) * (y2 - y1));
            const float v = inter / (a1 + garea - inter + 1e-8f);
            if (b == 0) iou0 = v; else iou1 = v;
        }
        // jnp.argmax takes first max on ties -> pick box 1 only if strictly greater
        const int bsel = (iou1 > iou0) ? 1 : 0;
        const float* s = p + 5 * bsel;

        const float gc  = t[4];
        const bool  obj = (gc != 0.0f);

        // ---- class loss: target[...,4:5] * (pred_cls - tgt_cls)^2, all cells ----
        float cls = 0.0f;
#pragma unroll
        for (int k = 0; k < 20; k++) {
            const float d = p[10 + k] - t[5 + k];
            cls = fmaf(d, d, cls);
        }
        loss = gc * cls;

        if (obj) {
            const float dx = s[0] - t[0];
            const float dy = s[1] - t[1];
            loss += 5.0f * (dx * dx + dy * dy);

            const float pw = s[2], ph = s[3];
            const float sgnw = (pw > 0.0f) ? 1.0f : ((pw < 0.0f) ? -1.0f : 0.0f);
            const float sgnh = (ph > 0.0f) ? 1.0f : ((ph < 0.0f) ? -1.0f : 0.0f);
            const float sw = sgnw * sqrtf(fabsf(pw) + 1e-8f) - sqrtf(gw);
            const float sh = sgnh * sqrtf(fabsf(ph) + 1e-8f) - sqrtf(gh);
            loss += 5.0f * (sw * sw + sh * sh);

            const float dc = s[4] - gc;
            loss += dc * dc;
        } else {
            const float d0 = p[4] - gc;
            const float d1 = p[9] - gc;
            loss += 0.5f * (d0 * d0 + d1 * d1);
        }
    }

    // ---- deterministic block reduction ----
    float v = warp_reduce(loss);
    const int wid = tid >> 5;
    const int lid = tid & 31;
    if (lid == 0) swarp[wid] = v;
    __syncthreads();
    if (tid == 0) {
        g_partials[blockIdx.x] = swarp[0] + swarp[1] + swarp[2] + swarp[3];
        // make the partial visible at L2, then take a ticket
        __threadfence();
        const unsigned int t = atomicAdd(&g_ticket, 1u);
        s_last = (t == (unsigned int)(nblocks - 1));
    }
    __syncthreads();

    if (s_last) {
        // All other blocks' partials are L2-visible (they fenced before the
        // ticket). Read via __ldcg to bypass non-coherent L1.
        float acc = 0.0f;
        for (int i = tid; i < nblocks; i += BLOCK) acc += __ldcg(&g_partials[i]);
        float r = warp_reduce(acc);
        if (lid == 0) swarp[wid] = r;
        __syncthreads();
        if (tid == 0) {
            out[0] = swarp[0] + swarp[1] + swarp[2] + swarp[3];
            g_ticket = 0;         // reset for next graph replay
            __threadfence();
        }
    }
}

extern "C" void kernel_launch(void* const* d_in, const int* in_sizes, int n_in,
                              void* d_out, int out_size)
{
    const float* pred = (const float*)d_in[0];
    const float* targ = (const float*)d_in[1];
    float* out = (float*)d_out;

    const int cells = in_sizes[0] / PRED_CH;          // N * 49
    const int nblocks = (cells + BLOCK - 1) / BLOCK;  // 6272 for N=16384

    yolo_loss_kernel<<<nblocks, BLOCK>>>(pred, targ, out, cells, nblocks);
}

// round 11
// speedup vs baseline: 1.1541x; 1.1541x over previous
#include <cuda_runtime.h>
#include <cstdint>

// YOLO-v1 style loss: S=7, B=2, C=20
// prediction: [N,7,7,30] f32, target: [N,7,7,25] f32 -> scalar f32
//
// Persistent CTAs (296 = 2/SM) + double-buffered cp.async staging so DRAM
// loads stay continuously in flight (R5 measured 51.5% DRAM: short-lived
// CTAs had zero outstanding loads during compute/barrier/tail phases).
// Deterministic single-kernel reduction via threadfence + ticket.
// Resubmitted unchanged pending a successful broker slot (audited 4x;
// no inter-block waits -> safe even under 1-CTA/SM placement).

#define S7 7
#define CELLS_PER_IMG 49
#define PRED_CH 30
#define TGT_CH 25
#define BLOCK 256
#define TILE 256
#define NSTAGE 2

#define STAGE_FLOATS (TILE * (PRED_CH + TGT_CH))      // 14080 floats = 56320 B
#define PRED_F4 ((TILE * PRED_CH) / 4)                // 1920
#define TGT_F4  ((TILE * TGT_CH) / 4)                 // 1600
#define TOT_F4  (PRED_F4 + TGT_F4)                    // 3520
#define SMEM_BYTES (NSTAGE * STAGE_FLOATS * 4)        // 112640 B dynamic

__device__ float g_partials[4096];
__device__ unsigned int g_ticket = 0;

__device__ __forceinline__ float warp_reduce(float v) {
#pragma unroll
    for (int o = 16; o > 0; o >>= 1) v += __shfl_down_sync(0xFFFFFFFFu, v, o);
    return v;
}

__device__ __forceinline__ void cp_async16(float* smem_dst, const float4* gsrc) {
    uint32_t s = (uint32_t)__cvta_generic_to_shared(smem_dst);
    asm volatile("cp.async.cg.shared.global [%0], [%1], 16;" :: "r"(s), "l"(gsrc));
}
#define CP_COMMIT() asm volatile("cp.async.commit_group;" ::: "memory")
#define CP_WAIT1()  asm volatile("cp.async.wait_group 1;" ::: "memory")

// Stage one tile (full or tail) into buffer `buf` (float* to stage base).
__device__ __forceinline__ void stage_tile(
    float* buf, const float* __restrict__ pred, const float* __restrict__ targ,
    int tile, int cells, int tid)
{
    const int base = tile * TILE;
    const int count = min(TILE, cells - base);
    float* sp = buf;
    float* st = buf + TILE * PRED_CH;
    if (count == TILE) {
        const float4* gp4 = (const float4*)(pred + (size_t)base * PRED_CH);
        const float4* gt4 = (const float4*)(targ + (size_t)base * TGT_CH);
#pragma unroll
        for (int r = 0; r < (TOT_F4 + BLOCK - 1) / BLOCK; r++) {   // 14 rounds
            const int j = r * BLOCK + tid;
            if (j < PRED_F4) {
                cp_async16(sp + 4 * j, gp4 + j);
            } else if (j < TOT_F4) {
                const int k = j - PRED_F4;
                cp_async16(st + 4 * k, gt4 + k);
            }
        }
    } else {
        // tail tile: synchronous scalar staging (ordered by the pipeline's
        // __syncthreads before compute of this buffer)
        const float* gp = pred + (size_t)base * PRED_CH;
        for (int j = tid; j < count * PRED_CH; j += BLOCK) sp[j] = gp[j];
        const float* gt = targ + (size_t)base * TGT_CH;
        for (int j = tid; j < count * TGT_CH; j += BLOCK) st[j] = gt[j];
    }
    CP_COMMIT();   // empty group in tail path keeps group accounting uniform
}

// Per-cell loss from staged tile.
__device__ __forceinline__ float cell_loss(const float* buf, int tile, int cells, int tid)
{
    const int base = tile * TILE;
    const int count = min(TILE, cells - base);
    if (tid >= count) return 0.0f;

    const float* p = buf + tid * PRED_CH;
    const float* t = buf + TILE * PRED_CH + tid * TGT_CH;

    const int gi   = base + tid;
    const int cell = gi % CELLS_PER_IMG;
    const float frow = (float)(cell / S7);
    const float fcol = (float)(cell % S7);

    // ground-truth corner box
    const float gw = t[2], gh = t[3];
    const float gcx = (t[0] + fcol) / 7.0f;
    const float gcy = (t[1] + frow) / 7.0f;
    const float gx1 = gcx - gw * 0.5f, gy1 = gcy - gh * 0.5f;
    const float gx2 = gcx + gw * 0.5f, gy2 = gcy + gh * 0.5f;
    const float garea = fabsf((gx2 - gx1) * (gy2 - gy1));

    // IOU for both predicted boxes
    float iou0 = 0.0f, iou1 = 0.0f;
#pragma unroll
    for (int b = 0; b < 2; b++) {
        const float* q = p + 5 * b;
        const float w = q[2], h = q[3];
        const float cx = (q[0] + fcol) / 7.0f;
        const float cy = (q[1] + frow) / 7.0f;
        const float x1 = cx - w * 0.5f, y1 = cy - h * 0.5f;
        const float x2 = cx + w * 0.5f, y2 = cy + h * 0.5f;
        const float ix1 = fmaxf(x1, gx1), iy1 = fmaxf(y1, gy1);
        const float ix2 = fminf(x2, gx2), iy2 = fminf(y2, gy2);
        const float inter = fmaxf(ix2 - ix1, 0.0f) * fmaxf(iy2 - iy1, 0.0f);
        const float a1 = fabsf((x2 - x1) * (y2 - y1));
        const float v = inter / (a1 + garea - inter + 1e-8f);
        if (b == 0) iou0 = v; else iou1 = v;
    }
    // jnp.argmax first-max tie-break -> box 1 only if strictly greater
    const int bsel = (iou1 > iou0) ? 1 : 0;
    const float* s = p + 5 * bsel;

    const float gc  = t[4];
    const bool  obj = (gc != 0.0f);

    // class loss (target conf scales it, applied in all cells)
    float cls = 0.0f;
#pragma unroll
    for (int k = 0; k < 20; k++) {
        const float d = p[10 + k] - t[5 + k];
        cls = fmaf(d, d, cls);
    }
    float loss = gc * cls;

    if (obj) {
        const float dx = s[0] - t[0];
        const float dy = s[1] - t[1];
        loss += 5.0f * (dx * dx + dy * dy);

        const float pw = s[2], ph = s[3];
        const float sgnw = (pw > 0.0f) ? 1.0f : ((pw < 0.0f) ? -1.0f : 0.0f);
        const float sgnh = (ph > 0.0f) ? 1.0f : ((ph < 0.0f) ? -1.0f : 0.0f);
        const float sw = sgnw * sqrtf(fabsf(pw) + 1e-8f) - sqrtf(gw);
        const float sh = sgnh * sqrtf(fabsf(ph) + 1e-8f) - sqrtf(gh);
        loss += 5.0f * (sw * sw + sh * sh);

        const float dc = s[4] - gc;
        loss += dc * dc;
    } else {
        const float d0 = p[4] - gc;
        const float d1 = p[9] - gc;
        loss += 0.5f * (d0 * d0 + d1 * d1);
    }
    return loss;
}

__global__ void __launch_bounds__(BLOCK) yolo_loss_kernel(
    const float* __restrict__ pred,
    const float* __restrict__ targ,
    float* __restrict__ out,
    int cells, int ntiles)
{
    extern __shared__ float smem_dyn[];     // NSTAGE * STAGE_FLOATS
    __shared__ float swarp[BLOCK / 32];
    __shared__ bool s_last;

    const int tid = threadIdx.x;
    const int bid = blockIdx.x;
    const int nblocks = gridDim.x;

    // tiles for this block: bid, bid+nblocks, ...
    const int nmine = (ntiles - bid + nblocks - 1) / nblocks;

    float acc = 0.0f;

    if (nmine > 0) {
        // prologue: stage first tile into buffer 0
        stage_tile(smem_dyn, pred, targ, bid, cells, tid);

        for (int i = 0; i < nmine; i++) {
            const int tile = bid + i * nblocks;
            // issue next tile's copies into the other buffer (or empty group)
            if (i + 1 < nmine) {
                stage_tile(smem_dyn + ((i + 1) & 1) * STAGE_FLOATS,
                           pred, targ, bid + (i + 1) * nblocks, cells, tid);
            } else {
                CP_COMMIT();
            }
            CP_WAIT1();          // buffer i&1 complete (<=1 group pending)
            __syncthreads();
            acc += cell_loss(smem_dyn + (i & 1) * STAGE_FLOATS, tile, cells, tid);
            __syncthreads();     // all reads of buffer i&1 done before reuse
        }
    }

    // deterministic block reduction
    float v = warp_reduce(acc);
    const int wid = tid >> 5;
    const int lid = tid & 31;
    if (lid == 0) swarp[wid] = v;
    __syncthreads();
    if (tid == 0) {
        float x = 0.0f;
#pragma unroll
        for (int w = 0; w < BLOCK / 32; w++) x += swarp[w];
        g_partials[bid] = x;
        __threadfence();
        const unsigned int t = atomicAdd(&g_ticket, 1u);
        s_last = (t == (unsigned int)(nblocks - 1));
    }
    __syncthreads();

    if (s_last) {
        float a = 0.0f;
        for (int i = tid; i < nblocks; i += BLOCK) a += __ldcg(&g_partials[i]);
        float r = warp_reduce(a);
        if (lid == 0) swarp[wid] = r;
        __syncthreads();
        if (tid == 0) {
            float x = 0.0f;
#pragma unroll
            for (int w = 0; w < BLOCK / 32; w++) x += swarp[w];
            out[0] = x;
            g_ticket = 0;       // reset for next graph replay
            __threadfence();
        }
    }
}

extern "C" void kernel_launch(void* const* d_in, const int* in_sizes, int n_in,
                              void* d_out, int out_size)
{
    const float* pred = (const float*)d_in[0];
    const float* targ = (const float*)d_in[1];
    float* out = (float*)d_out;

    const int cells  = in_sizes[0] / PRED_CH;            // N*49 = 802816
    const int ntiles = (cells + TILE - 1) / TILE;        // 3136

    // Unconditional (no static guard): idempotent, enqueues no work,
    // safe under graph capture.
    cudaFuncSetAttribute(yolo_loss_kernel,
                         cudaFuncAttributeMaxDynamicSharedMemorySize,
                         SMEM_BYTES);

    int nblocks = 296;                                   // 2 CTAs/SM * 148 SMs
    if (nblocks > ntiles) nblocks = ntiles;

    yolo_loss_kernel<<<nblocks, BLOCK, SMEM_BYTES>>>(pred, targ, out, cells, ntiles);
}